// round 9
// baseline (speedup 1.0000x reference)
#include <cuda_runtime.h>
#include <cuda_fp16.h>
#include <cstdint>

// HexConv, persistent-CTA fp16 mma.sync (m16n8k16, f32 accum), 2 CTAs/SM:
//   CTA holds zero-padded 13x17 hex grid of one batch in SMEM as fp16 (192 B/cell)
//   and all of W as fp16 (960 B/row). 8 warps = 4 M-groups x 2 N-halves (32 cols):
//   A fragments shared by only 2 warp groups (was 4), W amortized over 4 N-frags.
//   K-permutation: per 32-k superblock, thread lc owns orig d = 8lc..8lc+7 -> one
//   LDS.128 feeds two m16n8k16 k-steps; identical map for A and B.

#define NHEX   165
#define HD     64
#define OUTD   64
#define NCHUNK 7
#define CELLB  192           // bytes per padded cell (==64 mod 128 -> clean phases)
#define WROWB  960           // bytes per W row     (==64 mod 128)
#define NB     2048
#define THREADS 256
#define GRIDX  304

#define G_BYTES (221 * CELLB)           // 42432
#define W_BYTES (OUTD * WROWB)          // 61440
#define SMEM_BYTES (G_BYTES + W_BYTES)  // 103872

__constant__ int OFF0c[7] = {-17, -16, -1, 0, 1, 17, 18};   // even grid-row offsets

static __device__ __forceinline__ uint32_t pk(float a, float b) {
    __half2 h = __floats2half2_rn(a, b);
    return *(uint32_t*)&h;
}
static __device__ __forceinline__ void mma16816(float* c,
                                                uint32_t a0, uint32_t a1, uint32_t a2, uint32_t a3,
                                                uint32_t b0, uint32_t b1) {
    asm volatile(
        "mma.sync.aligned.m16n8k16.row.col.f32.f16.f16.f32 "
        "{%0,%1,%2,%3}, {%4,%5,%6,%7}, {%8,%9}, {%0,%1,%2,%3};"
        : "+f"(c[0]), "+f"(c[1]), "+f"(c[2]), "+f"(c[3])
        : "r"(a0), "r"(a1), "r"(a2), "r"(a3), "r"(b0), "r"(b1));
}

__global__ void __launch_bounds__(THREADS, 2)
hexconv_mma(const float* __restrict__ x, const float* __restrict__ W,
            const float* __restrict__ bias, float* __restrict__ out)
{
    extern __shared__ char smem[];
    char* Gc = smem;                     // padded grid, fp16
    char* Wc = smem + G_BYTES;           // W, fp16
    const int tid = threadIdx.x;

    // ---- one-time: zero padded grid ----
    for (int i = tid; i < G_BYTES / 16; i += THREADS)
        ((uint4*)Gc)[i] = make_uint4(0, 0, 0, 0);

    // ---- one-time: stage W as fp16 ----
    const float4* Wg4 = (const float4*)W;
    for (int i = tid; i < OUTD * 112; i += THREADS) {
        int o = i / 112, k4 = i - o * 112;
        float4 v = Wg4[i];
        *(uint2*)(Wc + o * WROWB + k4 * 8) = make_uint2(pk(v.x, v.y), pk(v.z, v.w));
    }

    // ---- warp geometry: 8 warps = 4 M-groups x 2 N-halves ----
    const int wid = tid >> 5, lane = tid & 31;
    const int wm = wid & 3;        // M group: frags f = wm + 4u
    const int wn = wid >> 2;       // N half (32 cols)
    const int lr = lane >> 2, lc = lane & 3;

    float2 bv[4];
#pragma unroll
    for (int nf = 0; nf < 4; nf++)
        bv[nf] = ((const float2*)bias)[(wn * 32 + nf * 8 + 2 * lc) >> 1];

    // per-thread fragment row bases (clamped): rows n = 16f + h*8 + lr
    int bc[3][2], par[3][2];
#pragma unroll
    for (int u = 0; u < 3; u++) {
        const int f = wm + 4 * u;
#pragma unroll
        for (int h = 0; h < 2; h++) {
            int n = f * 16 + h * 8 + lr;
            if (n > 164) n = 164;
            int hr = n / 15, hc = n - 15 * hr;
            bc[u][h]  = (hr + 1) * 17 + (hc + 1);
            par[u][h] = (hr + 1) & 1;
        }
    }

    // ---- staging maps: 1320 groups of 8 floats; first 768 prefetched in regs ----
    int gdst[6];
#pragma unroll
    for (int j = 0; j < 6; j++) {
        int g = tid + THREADS * j;
        if (g < NHEX * 8) {
            int n = g >> 3, d8 = g & 7;
            int hr = n / 15, hc = n - 15 * hr;
            gdst[j] = ((hr + 1) * 17 + (hc + 1)) * CELLB + d8 * 16;
        } else gdst[j] = -1;
    }
    float4 pf[3][2];
    {
        const float4* xb4 = (const float4*)(x + (size_t)blockIdx.x * (NHEX * HD));
#pragma unroll
        for (int j = 0; j < 3; j++) {
            int g = tid + THREADS * j;
            pf[j][0] = xb4[2 * g];
            pf[j][1] = xb4[2 * g + 1];
        }
    }
    __syncthreads();   // zeroing complete before first STS

    for (int b = blockIdx.x; b < NB; b += GRIDX) {
        const float4* xb4 = (const float4*)(x + (size_t)b * (NHEX * HD));
        // ---- convert prefetched regs -> fp16 grid ----
#pragma unroll
        for (int j = 0; j < 3; j++) {
            uint4 o;
            o.x = pk(pf[j][0].x, pf[j][0].y);
            o.y = pk(pf[j][0].z, pf[j][0].w);
            o.z = pk(pf[j][1].x, pf[j][1].y);
            o.w = pk(pf[j][1].z, pf[j][1].w);
            *(uint4*)(Gc + gdst[j]) = o;
        }
        // ---- remaining groups: direct load + convert ----
#pragma unroll
        for (int j = 3; j < 6; j++)
            if (gdst[j] >= 0) {
                int g = tid + THREADS * j;
                float4 v0 = xb4[2 * g], v1 = xb4[2 * g + 1];
                uint4 o;
                o.x = pk(v0.x, v0.y);
                o.y = pk(v0.z, v0.w);
                o.z = pk(v1.x, v1.y);
                o.w = pk(v1.z, v1.w);
                *(uint4*)(Gc + gdst[j]) = o;
            }
        __syncthreads();   // grid ready

        // ---- prefetch next batch (overlaps with compute) ----
        const int bn = b + GRIDX;
        if (bn < NB) {
            const float4* xn4 = (const float4*)(x + (size_t)bn * (NHEX * HD));
#pragma unroll
            for (int j = 0; j < 3; j++) {
                int g = tid + THREADS * j;
                pf[j][0] = xn4[2 * g];
                pf[j][1] = xn4[2 * g + 1];
            }
        }

        float acc[3][4][4];
#pragma unroll
        for (int u = 0; u < 3; u++)
#pragma unroll
            for (int nf = 0; nf < 4; nf++)
#pragma unroll
                for (int i = 0; i < 4; i++) acc[u][nf][i] = 0.f;

        const char* Wp0 = Wc + (wn * 32 + lr) * WROWB + 16 * lc;

#pragma unroll 1
        for (int c = 0; c < NCHUNK; c++) {
            const int off  = OFF0c[c];
            const int adjc = (c < 2 || c > 4) ? 1 : 0;
            int pA[3][2];
#pragma unroll
            for (int u = 0; u < 3; u++)
#pragma unroll
                for (int h = 0; h < 2; h++)
                    pA[u][h] = (bc[u][h] + off - (adjc ? par[u][h] : 0)) * CELLB + 16 * lc;

#pragma unroll
            for (int sb = 0; sb < 2; sb++) {
                const int cb = c * 128 + sb * 64;
                uint4 w[4];
#pragma unroll
                for (int nf = 0; nf < 4; nf++)
                    w[nf] = *(const uint4*)(Wp0 + nf * (8 * WROWB) + cb);
#pragma unroll
                for (int u = 0; u < 3; u++) {
                    if (u < 2 || wm < 3) {
                        uint4 va = *(const uint4*)(Gc + pA[u][0] + sb * 64);
                        uint4 vb = *(const uint4*)(Gc + pA[u][1] + sb * 64);
#pragma unroll
                        for (int nf = 0; nf < 4; nf++) {
                            mma16816(acc[u][nf], va.x, vb.x, va.y, vb.y, w[nf].x, w[nf].y);
                            mma16816(acc[u][nf], va.z, vb.z, va.w, vb.w, w[nf].z, w[nf].w);
                        }
                    }
                }
            }
        }

        // ---- epilogue: bias + masked stores ----
        float* ob = out + (size_t)b * (NHEX * OUTD);
#pragma unroll
        for (int u = 0; u < 3; u++) {
            if (u < 2 || wm < 3) {
                const int f = wm + 4 * u;
                const int n1 = f * 16 + lr, n2 = n1 + 8;
#pragma unroll
                for (int nf = 0; nf < 4; nf++) {
                    const int cc = wn * 32 + nf * 8 + 2 * lc;
                    if (n1 < NHEX) {
                        float2 v = make_float2(acc[u][nf][0] + bv[nf].x,
                                               acc[u][nf][1] + bv[nf].y);
                        *(float2*)(ob + n1 * OUTD + cc) = v;
                    }
                    if (n2 < NHEX) {
                        float2 v = make_float2(acc[u][nf][2] + bv[nf].x,
                                               acc[u][nf][3] + bv[nf].y);
                        *(float2*)(ob + n2 * OUTD + cc) = v;
                    }
                }
            }
        }
        __syncthreads();   // all warps done reading G before next STS
    }
}

extern "C" void kernel_launch(void* const* d_in, const int* in_sizes, int n_in,
                              void* d_out, int out_size)
{
    const float* x    = (const float*)d_in[0];
    const float* W    = (const float*)d_in[1];
    const float* bias = (const float*)d_in[2];
    float* out = (float*)d_out;

    cudaFuncSetAttribute(hexconv_mma,
                         cudaFuncAttributeMaxDynamicSharedMemorySize,
                         (int)SMEM_BYTES);
    hexconv_mma<<<GRIDX, THREADS, SMEM_BYTES>>>(x, W, bias, out);
}

// round 10
// speedup vs baseline: 1.5242x; 1.5242x over previous
#include <cuda_runtime.h>
#include <cuda_fp16.h>
#include <cstdint>

// HexConv, persistent-CTA fp16 mma.sync (m16n8k16, f32 accum) — round-8 structure
// with MLP-restructured mainloop:
//   per chunk c: load all 4 W frags (LDS.128 x4), then per m-group u load all 4 A
//   frags (LDS.128 x4) and issue 8 MMAs. 4-wide load batches instead of 2-wide.
// 16 warps = 4(N quarters of 16) x 4(M groups); frags f = wm + 4u (11, tail masked).
// K-permutation: per 32-k superblock, thread lc owns orig d = 8lc..8lc+7.

#define NHEX   165
#define HD     64
#define OUTD   64
#define NCHUNK 7
#define CELLB  192           // bytes per padded cell (==64 mod 128)
#define WROWB  960           // bytes per W row     (==64 mod 128)
#define NB     2048
#define THREADS 512
#define GRIDX  152

#define G_BYTES (221 * CELLB)           // 42432
#define W_BYTES (OUTD * WROWB)          // 61440
#define SMEM_BYTES (G_BYTES + W_BYTES)  // 103872

__constant__ int OFFC[7] = {-17 * CELLB, -16 * CELLB, -1 * CELLB, 0,
                            1 * CELLB, 17 * CELLB, 18 * CELLB};

static __device__ __forceinline__ uint32_t pk(float a, float b) {
    __half2 h = __floats2half2_rn(a, b);
    return *(uint32_t*)&h;
}
static __device__ __forceinline__ void mma16816(float* c,
                                                uint32_t a0, uint32_t a1, uint32_t a2, uint32_t a3,
                                                uint32_t b0, uint32_t b1) {
    asm volatile(
        "mma.sync.aligned.m16n8k16.row.col.f32.f16.f16.f32 "
        "{%0,%1,%2,%3}, {%4,%5,%6,%7}, {%8,%9}, {%0,%1,%2,%3};"
        : "+f"(c[0]), "+f"(c[1]), "+f"(c[2]), "+f"(c[3])
        : "r"(a0), "r"(a1), "r"(a2), "r"(a3), "r"(b0), "r"(b1));
}

__global__ void __launch_bounds__(THREADS, 1)
hexconv_mma(const float* __restrict__ x, const float* __restrict__ W,
            const float* __restrict__ bias, float* __restrict__ out)
{
    extern __shared__ char smem[];
    char* Gc = smem;                     // padded grid, fp16
    char* Wc = smem + G_BYTES;           // W, fp16
    const int tid = threadIdx.x;

    // ---- one-time: zero padded grid ----
    for (int i = tid; i < G_BYTES / 16; i += THREADS)
        ((uint4*)Gc)[i] = make_uint4(0, 0, 0, 0);

    // ---- one-time: stage W as fp16 ----
    const float4* Wg4 = (const float4*)W;
    for (int i = tid; i < OUTD * 112; i += THREADS) {
        int o = i / 112, k4 = i - o * 112;
        float4 v = Wg4[i];
        *(uint2*)(Wc + o * WROWB + k4 * 8) = make_uint2(pk(v.x, v.y), pk(v.z, v.w));
    }

    // ---- warp geometry ----
    const int wid = tid >> 5, lane = tid & 31;
    const int wm = wid & 3;        // M group: frags f = wm + 4u
    const int wn = wid >> 2;       // N quarter (16 cols)
    const int lr = lane >> 2, lc = lane & 3;

    float2 bv[2];
#pragma unroll
    for (int nf = 0; nf < 2; nf++)
        bv[nf] = ((const float2*)bias)[(wn * 16 + nf * 8 + 2 * lc) >> 1];

    // per-thread fragment row bases (clamped): rows n = 16f + h*8 + lr
    int base2[3][2];   // cell*CELLB + 16*lc
    int parC[3][2];    // (padded row odd ? CELLB : 0)
#pragma unroll
    for (int u = 0; u < 3; u++) {
        const int f = wm + 4 * u;
#pragma unroll
        for (int h = 0; h < 2; h++) {
            int n = f * 16 + h * 8 + lr;
            if (n > 164) n = 164;
            int hr = n / 15, hc = n - 15 * hr;
            base2[u][h] = (((hr + 1) * 17 + (hc + 1))) * CELLB + 16 * lc;
            parC[u][h]  = ((hr + 1) & 1) ? CELLB : 0;
        }
    }

    // ---- staging maps: 1320 groups of 8 floats; <=3 per thread, reg-prefetched ----
    float4 pf[3][2];
    int gdst[3];
#pragma unroll
    for (int j = 0; j < 3; j++) {
        int g = tid + THREADS * j;
        if (g < NHEX * 8) {
            int n = g >> 3, d8 = g & 7;
            int hr = n / 15, hc = n - 15 * hr;
            gdst[j] = ((hr + 1) * 17 + (hc + 1)) * CELLB + d8 * 16;
        } else gdst[j] = -1;
    }
    {
        const float4* xb4 = (const float4*)(x + (size_t)blockIdx.x * (NHEX * HD));
#pragma unroll
        for (int j = 0; j < 3; j++)
            if (gdst[j] >= 0) {
                int g = tid + THREADS * j;
                pf[j][0] = xb4[2 * g];
                pf[j][1] = xb4[2 * g + 1];
            }
    }
    __syncthreads();   // zeroing complete before first STS

    for (int b = blockIdx.x; b < NB; b += GRIDX) {
        // ---- convert prefetched regs -> fp16 grid ----
#pragma unroll
        for (int j = 0; j < 3; j++)
            if (gdst[j] >= 0) {
                uint4 o;
                o.x = pk(pf[j][0].x, pf[j][0].y);
                o.y = pk(pf[j][0].z, pf[j][0].w);
                o.z = pk(pf[j][1].x, pf[j][1].y);
                o.w = pk(pf[j][1].z, pf[j][1].w);
                *(uint4*)(Gc + gdst[j]) = o;
            }
        __syncthreads();   // grid ready

        // ---- prefetch next batch (overlaps with compute) ----
        const int bn = b + GRIDX;
        if (bn < NB) {
            const float4* xn4 = (const float4*)(x + (size_t)bn * (NHEX * HD));
#pragma unroll
            for (int j = 0; j < 3; j++)
                if (gdst[j] >= 0) {
                    int g = tid + THREADS * j;
                    pf[j][0] = xn4[2 * g];
                    pf[j][1] = xn4[2 * g + 1];
                }
        }

        float acc[3][2][4];
#pragma unroll
        for (int u = 0; u < 3; u++)
#pragma unroll
            for (int nf = 0; nf < 2; nf++)
#pragma unroll
                for (int i = 0; i < 4; i++) acc[u][nf][i] = 0.f;

        const char* Wp0 = Wc + (wn * 16 + lr) * WROWB + 16 * lc;

#pragma unroll 1
        for (int c = 0; c < NCHUNK; c++) {
            const int off  = OFFC[c];
            const bool adj = (c < 2 || c > 4);

            // ---- all 4 W frags of this chunk up front (4-wide MLP) ----
            const char* wp = Wp0 + c * 128;
            uint4 w00 = *(const uint4*)(wp);
            uint4 w01 = *(const uint4*)(wp + 64);
            uint4 w10 = *(const uint4*)(wp + 8 * WROWB);
            uint4 w11 = *(const uint4*)(wp + 8 * WROWB + 64);

#pragma unroll
            for (int u = 0; u < 3; u++) {
                if (u < 2 || wm < 3) {
                    const int p0 = base2[u][0] + off - (adj ? parC[u][0] : 0);
                    const int p1 = base2[u][1] + off - (adj ? parC[u][1] : 0);
                    // ---- all 4 A frags of this m-group (4-wide MLP) ----
                    uint4 a00 = *(const uint4*)(Gc + p0);
                    uint4 a01 = *(const uint4*)(Gc + p0 + 64);
                    uint4 a10 = *(const uint4*)(Gc + p1);
                    uint4 a11 = *(const uint4*)(Gc + p1 + 64);
                    // sub-block 0
                    mma16816(acc[u][0], a00.x, a10.x, a00.y, a10.y, w00.x, w00.y);
                    mma16816(acc[u][1], a00.x, a10.x, a00.y, a10.y, w10.x, w10.y);
                    mma16816(acc[u][0], a00.z, a10.z, a00.w, a10.w, w00.z, w00.w);
                    mma16816(acc[u][1], a00.z, a10.z, a00.w, a10.w, w10.z, w10.w);
                    // sub-block 1
                    mma16816(acc[u][0], a01.x, a11.x, a01.y, a11.y, w01.x, w01.y);
                    mma16816(acc[u][1], a01.x, a11.x, a01.y, a11.y, w11.x, w11.y);
                    mma16816(acc[u][0], a01.z, a11.z, a01.w, a11.w, w01.z, w01.w);
                    mma16816(acc[u][1], a01.z, a11.z, a01.w, a11.w, w11.z, w11.w);
                }
            }
        }

        // ---- epilogue: bias + masked stores ----
        float* ob = out + (size_t)b * (NHEX * OUTD);
#pragma unroll
        for (int u = 0; u < 3; u++) {
            if (u < 2 || wm < 3) {
                const int f = wm + 4 * u;
                const int n1 = f * 16 + lr, n2 = n1 + 8;
#pragma unroll
                for (int nf = 0; nf < 2; nf++) {
                    const int cc = wn * 16 + nf * 8 + 2 * lc;
                    if (n1 < NHEX) {
                        float2 v = make_float2(acc[u][nf][0] + bv[nf].x,
                                               acc[u][nf][1] + bv[nf].y);
                        *(float2*)(ob + n1 * OUTD + cc) = v;
                    }
                    if (n2 < NHEX) {
                        float2 v = make_float2(acc[u][nf][2] + bv[nf].x,
                                               acc[u][nf][3] + bv[nf].y);
                        *(float2*)(ob + n2 * OUTD + cc) = v;
                    }
                }
            }
        }
        __syncthreads();   // all warps done reading G before next STS
    }
}

extern "C" void kernel_launch(void* const* d_in, const int* in_sizes, int n_in,
                              void* d_out, int out_size)
{
    const float* x    = (const float*)d_in[0];
    const float* W    = (const float*)d_in[1];
    const float* bias = (const float*)d_in[2];
    float* out = (float*)d_out;

    cudaFuncSetAttribute(hexconv_mma,
                         cudaFuncAttributeMaxDynamicSharedMemorySize,
                         (int)SMEM_BYTES);
    hexconv_mma<<<GRIDX, THREADS, SMEM_BYTES>>>(x, W, bias, out);
}